// round 3
// baseline (speedup 1.0000x reference)
#include <cuda_runtime.h>

#define DIMX   240
#define NTYPE  10
#define NSLOT  176   // per type: 64 scalar sums, 64 scalar sumsq, 32 vec sumsq, 16 l2 sumsq
#define EPSV   1e-5f

__device__ float g_acc[NTYPE * NSLOT];
__device__ float g_cnt[NTYPE];
__device__ float g_A[NTYPE * DIMX];
__device__ float g_C[NTYPE * DIMX];

__global__ void k_zero() {
    int i = blockIdx.x * blockDim.x + threadIdx.x;
    if (i < NTYPE * NSLOT) g_acc[i] = 0.0f;
    if (i < NTYPE) g_cnt[i] = 0.0f;
}

__global__ void k_count(const int* __restrict__ tp, int batch) {
    __shared__ int h[NTYPE];
    if (threadIdx.x < NTYPE) h[threadIdx.x] = 0;
    __syncthreads();
    for (int i = blockIdx.x * blockDim.x + threadIdx.x; i < batch;
         i += gridDim.x * blockDim.x) {
        atomicAdd(&h[tp[i]], 1);
    }
    __syncthreads();
    if (threadIdx.x < NTYPE) atomicAdd(&g_cnt[threadIdx.x], (float)h[threadIdx.x]);
}

// 128 threads cover all 240 columns: thread c handles column c, and column c+128 if c<112.
// Per-row type is warp-uniform, so the 10-way predicated accumulate has uniform predicates.
__global__ void __launch_bounds__(128, 8)
k_reduce(const float* __restrict__ x, const int* __restrict__ tp, int batch) {
    const int c = threadIdx.x;
    const bool sc = (c < 64);    // scalar column (warp-uniform: warps 0,1)
    const bool h2 = (c < 112);   // has second column
    const int c2 = c + 128;

    float a0[NTYPE], a1[NTYPE], a2[NTYPE];
#pragma unroll
    for (int k = 0; k < NTYPE; k++) { a0[k] = 0.f; a1[k] = 0.f; a2[k] = 0.f; }

    for (int row = blockIdx.x; row < batch; row += gridDim.x) {
        const int t = __ldg(tp + row);
        const float* xr = x + (long long)row * DIMX;
        const float v  = __ldg(xr + c);
        const float v2 = h2 ? __ldg(xr + c2) : 0.0f;
        const float s  = v * v;
        const float s2 = v2 * v2;
        if (sc) {
#pragma unroll
            for (int k = 0; k < NTYPE; k++)
                if (t == k) { a0[k] += v; a1[k] += s; a2[k] += s2; }
        } else {
#pragma unroll
            for (int k = 0; k < NTYPE; k++)
                if (t == k) { a0[k] += s; a2[k] += s2; }
        }
    }

    // slot mapping for the flush
    int slot0 = 0;
    if (!sc) slot0 = (c < 160) ? (128 + (c - 64) / 3) : (160 + (c - 160) / 5);
    const int slot2 = (c2 < 160) ? (128 + (c2 - 64) / 3) : (160 + (c2 - 160) / 5);

#pragma unroll
    for (int k = 0; k < NTYPE; k++) {
        float* g = g_acc + k * NSLOT;
        if (sc) {
            atomicAdd(g + c, a0[k]);
            atomicAdd(g + 64 + c, a1[k]);
        } else {
            atomicAdd(g + slot0, a0[k]);
        }
        if (h2) atomicAdd(g + slot2, a2[k]);
    }
}

__global__ void k_stats(const float* __restrict__ w, const float* __restrict__ b) {
    const int t = blockIdx.x;
    const int c = threadIdx.x;
    const float cnt = fmaxf(g_cnt[t], 1.0f);
    const float* acc = g_acc + t * NSLOT;
    float A, C;
    if (c < 64) {
        const float fm  = acc[c] / cnt;
        const float var = acc[64 + c] / cnt - fm * fm;
        const float s   = rsqrtf(var + EPSV) * w[t * 112 + c];
        A = s;
        C = b[t * 64 + c] - fm * s;
    } else if (c < 160) {
        const int m = (c - 64) / 3;
        const float fn = acc[128 + m] / (3.0f * cnt);
        A = rsqrtf(fn + EPSV) * w[t * 112 + 64 + m];
        C = 0.0f;
    } else {
        const int m = (c - 160) / 5;
        const float fn = acc[160 + m] / (5.0f * cnt);
        A = rsqrtf(fn + EPSV) * w[t * 112 + 96 + m];
        C = 0.0f;
    }
    g_A[t * DIMX + c] = A;
    g_C[t * DIMX + c] = C;
}

// out = x * A[type][col] + C[type][col], float4 vectorized (240 = 60 float4 per row)
__global__ void __launch_bounds__(256)
k_apply(const float4* __restrict__ x4, const int* __restrict__ tp,
        float4* __restrict__ o4, int n4) {
    __shared__ __align__(16) float sA[NTYPE * DIMX];
    __shared__ __align__(16) float sC[NTYPE * DIMX];
    for (int i = threadIdx.x; i < NTYPE * DIMX; i += blockDim.x) {
        sA[i] = g_A[i];
        sC[i] = g_C[i];
    }
    __syncthreads();

    const int stride = gridDim.x * blockDim.x;
    for (int i = blockIdx.x * blockDim.x + threadIdx.x; i < n4; i += stride) {
        const int row = i / 60;
        const int q   = i - row * 60;
        const int t   = __ldg(tp + row);
        const float4 xv = x4[i];
        const float4 a  = *((const float4*)(sA + t * DIMX) + q);
        const float4 cc = *((const float4*)(sC + t * DIMX) + q);
        float4 r;
        r.x = fmaf(xv.x, a.x, cc.x);
        r.y = fmaf(xv.y, a.y, cc.y);
        r.z = fmaf(xv.z, a.z, cc.z);
        r.w = fmaf(xv.w, a.w, cc.w);
        o4[i] = r;
    }
}

extern "C" void kernel_launch(void* const* d_in, const int* in_sizes, int n_in,
                              void* d_out, int out_size) {
    const float* x  = (const float*)d_in[0];
    const int*   tp = (const int*)d_in[1];
    const float* w  = (const float*)d_in[2];
    const float* b  = (const float*)d_in[3];
    float* out = (float*)d_out;
    const int batch = in_sizes[1];

    k_zero<<<7, 256>>>();
    k_count<<<148, 256>>>(tp, batch);
    k_reduce<<<1184, 128>>>(x, tp, batch);
    k_stats<<<NTYPE, DIMX>>>(w, b);
    const int n4 = batch * (DIMX / 4);
    k_apply<<<1184, 256>>>((const float4*)x, tp, (float4*)out, n4);
}

// round 5
// speedup vs baseline: 1.0448x; 1.0448x over previous
#include <cuda_runtime.h>

#define DIMX   240
#define NTYPE  10
#define NSLOT  176   // per type: 64 scalar sums, 64 scalar sumsq, 32 vec sumsq, 16 l2 sumsq
#define EPSV   1e-5f
#define MAXB   200704
#define CHUNK  256

__device__ float g_acc[NTYPE * NSLOT];
__device__ int   g_cnti[NTYPE];
__device__ int   g_off[NTYPE + 1];
__device__ int   g_cursor[NTYPE];
__device__ int   g_perm[MAXB];
__device__ float g_A[NTYPE * DIMX];
__device__ float g_C[NTYPE * DIMX];

__global__ void k_zero() {
    int i = blockIdx.x * blockDim.x + threadIdx.x;
    if (i < NTYPE * NSLOT) g_acc[i] = 0.0f;
    if (i < NTYPE) g_cnti[i] = 0;
}

__global__ void k_hist(const int* __restrict__ tp, int batch) {
    __shared__ int h[NTYPE];
    if (threadIdx.x < NTYPE) h[threadIdx.x] = 0;
    __syncthreads();
    for (int i = blockIdx.x * blockDim.x + threadIdx.x; i < batch;
         i += gridDim.x * blockDim.x) {
        atomicAdd(&h[tp[i]], 1);
    }
    __syncthreads();
    if (threadIdx.x < NTYPE) atomicAdd(&g_cnti[threadIdx.x], h[threadIdx.x]);
}

__global__ void k_scan() {
    if (threadIdx.x == 0) {
        int o = 0;
        for (int t = 0; t < NTYPE; t++) {
            g_off[t] = o;
            g_cursor[t] = o;
            o += g_cnti[t];
        }
        g_off[NTYPE] = o;
    }
}

// Counting-sort scatter: order within a bucket is irrelevant (sum reduction),
// so each block reserves a per-type range with ONE global atomic per type.
__global__ void k_scatter(const int* __restrict__ tp, int batch) {
    __shared__ int h[NTYPE], base[NTYPE];
    if (threadIdx.x < NTYPE) h[threadIdx.x] = 0;
    __syncthreads();
    const int i = blockIdx.x * blockDim.x + threadIdx.x;
    int t = 0, loc = 0;
    if (i < batch) {
        t = tp[i];
        loc = atomicAdd(&h[t], 1);
    }
    __syncthreads();
    if (threadIdx.x < NTYPE && h[threadIdx.x] > 0)
        base[threadIdx.x] = atomicAdd(&g_cursor[threadIdx.x], h[threadIdx.x]);
    __syncthreads();
    if (i < batch) g_perm[base[t] + loc] = i;
}

// Each block processes one CHUNK of bucket-sorted positions. Within a same-type
// run only 3 register accumulators are live; atomics only at run boundaries.
__global__ void __launch_bounds__(128, 8)
k_reduce2(const float* __restrict__ x, int batch) {
    __shared__ int soff[NTYPE + 1];
    __shared__ int sperm[CHUNK];
    const int c = threadIdx.x;
    if (c <= NTYPE) soff[c] = g_off[c];
    const int pstart = blockIdx.x * CHUNK;
    const int pend = min(pstart + CHUNK, batch);
    for (int j = c; j < pend - pstart; j += 128) sperm[j] = g_perm[pstart + j];
    __syncthreads();

    const bool sc = (c < 64);
    const bool h2 = (c < 112);
    const int c2 = c + 128;

    int curt = 0;
    while (pstart >= soff[curt + 1]) curt++;

    int p = pstart;
    while (p < pend) {
        const int rend = min(pend, soff[curt + 1]);
        float s0 = 0.f, s1 = 0.f, s2 = 0.f;
#pragma unroll 4
        for (int q = p; q < rend; q++) {
            const int row = sperm[q - pstart];
            const float* xr = x + (long long)row * DIMX;
            const float v  = __ldg(xr + c);
            const float v2 = h2 ? __ldg(xr + c2) : 0.0f;
            if (sc) {
                s0 += v;
                s1 = fmaf(v, v, s1);
            } else {
                s0 = fmaf(v, v, s0);
            }
            s2 = fmaf(v2, v2, s2);
        }
        float* g = g_acc + curt * NSLOT;
        if (sc) {
            atomicAdd(g + c, s0);
            atomicAdd(g + 64 + c, s1);
        } else {
            const int slot0 = (c < 160) ? (128 + (c - 64) / 3) : (160 + (c - 160) / 5);
            atomicAdd(g + slot0, s0);
        }
        if (h2) {
            const int slot2 = (c2 < 160) ? (128 + (c2 - 64) / 3) : (160 + (c2 - 160) / 5);
            atomicAdd(g + slot2, s2);
        }
        p = rend;
        if (p < pend) {
            while (p >= soff[curt + 1]) curt++;
        }
    }
}

__global__ void k_stats(const float* __restrict__ w, const float* __restrict__ b) {
    const int t = blockIdx.x;
    const int c = threadIdx.x;
    const float cnt = fmaxf((float)g_cnti[t], 1.0f);
    const float* acc = g_acc + t * NSLOT;
    float A, C;
    if (c < 64) {
        const float fm  = acc[c] / cnt;
        const float var = acc[64 + c] / cnt - fm * fm;
        const float s   = rsqrtf(var + EPSV) * w[t * 112 + c];
        A = s;
        C = b[t * 64 + c] - fm * s;
    } else if (c < 160) {
        const int m = (c - 64) / 3;
        const float fn = acc[128 + m] / (3.0f * cnt);
        A = rsqrtf(fn + EPSV) * w[t * 112 + 64 + m];
        C = 0.0f;
    } else {
        const int m = (c - 160) / 5;
        const float fn = acc[160 + m] / (5.0f * cnt);
        A = rsqrtf(fn + EPSV) * w[t * 112 + 96 + m];
        C = 0.0f;
    }
    g_A[t * DIMX + c] = A;
    g_C[t * DIMX + c] = C;
}

// out = x * A[type][col] + C[type][col], float4 vectorized (240 = 60 float4 per row)
__global__ void __launch_bounds__(256)
k_apply(const float4* __restrict__ x4, const int* __restrict__ tp,
        float4* __restrict__ o4, int n4) {
    __shared__ __align__(16) float sA[NTYPE * DIMX];
    __shared__ __align__(16) float sC[NTYPE * DIMX];
    for (int i = threadIdx.x; i < NTYPE * DIMX; i += blockDim.x) {
        sA[i] = g_A[i];
        sC[i] = g_C[i];
    }
    __syncthreads();

    const int stride = gridDim.x * blockDim.x;
    for (int i = blockIdx.x * blockDim.x + threadIdx.x; i < n4; i += stride) {
        const int row = i / 60;
        const int q   = i - row * 60;
        const int t   = __ldg(tp + row);
        const float4 xv = x4[i];
        const float4 a  = *((const float4*)(sA + t * DIMX) + q);
        const float4 cc = *((const float4*)(sC + t * DIMX) + q);
        float4 r;
        r.x = fmaf(xv.x, a.x, cc.x);
        r.y = fmaf(xv.y, a.y, cc.y);
        r.z = fmaf(xv.z, a.z, cc.z);
        r.w = fmaf(xv.w, a.w, cc.w);
        o4[i] = r;
    }
}

extern "C" void kernel_launch(void* const* d_in, const int* in_sizes, int n_in,
                              void* d_out, int out_size) {
    const float* x  = (const float*)d_in[0];
    const int*   tp = (const int*)d_in[1];
    const float* w  = (const float*)d_in[2];
    const float* b  = (const float*)d_in[3];
    float* out = (float*)d_out;
    const int batch = in_sizes[1];

    const int nsb = (batch + CHUNK - 1) / CHUNK;

    k_zero<<<7, 256>>>();
    k_hist<<<296, 256>>>(tp, batch);
    k_scan<<<1, 32>>>();
    k_scatter<<<nsb, 256>>>(tp, batch);
    k_reduce2<<<nsb, 128>>>(x, batch);
    k_stats<<<NTYPE, DIMX>>>(w, b);
    const int n4 = batch * (DIMX / 4);
    k_apply<<<1184, 256>>>((const float4*)x, tp, (float4*)out, n4);
}

// round 7
// speedup vs baseline: 1.0521x; 1.0070x over previous
#include <cuda_runtime.h>

#define DIMX   240
#define NTYPE  10
#define NSLOT  176   // per type: 64 scalar sums, 64 scalar sumsq, 32 vec sumsq, 16 l2 sumsq
#define EPSV   1e-5f
#define MAXB   200704
#define CHUNK  256

__device__ float g_acc[NTYPE * NSLOT];
__device__ int   g_cnti[NTYPE];
__device__ int   g_cursor[NTYPE];
__device__ int   g_perm[MAXB];
__device__ float g_A[NTYPE * DIMX];
__device__ float g_C[NTYPE * DIMX];

__global__ void k_zero() {
    int i = blockIdx.x * blockDim.x + threadIdx.x;
    if (i < NTYPE * NSLOT) g_acc[i] = 0.0f;
    if (i < NTYPE) { g_cnti[i] = 0; g_cursor[i] = 0; }
}

__global__ void k_hist(const int* __restrict__ tp, int batch) {
    __shared__ int h[NTYPE];
    if (threadIdx.x < NTYPE) h[threadIdx.x] = 0;
    __syncthreads();
    for (int i = blockIdx.x * blockDim.x + threadIdx.x; i < batch;
         i += gridDim.x * blockDim.x) {
        atomicAdd(&h[tp[i]], 1);
    }
    __syncthreads();
    if (threadIdx.x < NTYPE) atomicAdd(&g_cnti[threadIdx.x], h[threadIdx.x]);
}

// Counting-sort scatter with inline 10-element scan of g_cnti (no separate k_scan).
__global__ void k_scatter(const int* __restrict__ tp, int batch) {
    __shared__ int h[NTYPE], base[NTYPE], soff[NTYPE];
    if (threadIdx.x < NTYPE) {
        h[threadIdx.x] = 0;
        int o = 0;
        for (int k = 0; k < threadIdx.x; k++) o += g_cnti[k];
        soff[threadIdx.x] = o;
    }
    __syncthreads();
    const int i = blockIdx.x * blockDim.x + threadIdx.x;
    int t = 0, loc = 0;
    if (i < batch) {
        t = tp[i];
        loc = atomicAdd(&h[t], 1);
    }
    __syncthreads();
    if (threadIdx.x < NTYPE && h[threadIdx.x] > 0)
        base[threadIdx.x] = soff[threadIdx.x] + atomicAdd(&g_cursor[threadIdx.x], h[threadIdx.x]);
    __syncthreads();
    if (i < batch) g_perm[base[t] + loc] = i;
}

// Each block processes one CHUNK of bucket-sorted positions. Within a same-type
// run only 3 register accumulators are live; atomics only at run boundaries.
__global__ void __launch_bounds__(128, 8)
k_reduce2(const float* __restrict__ x, int batch) {
    __shared__ int soff[NTYPE + 1];
    __shared__ int sperm[CHUNK];
    const int c = threadIdx.x;
    if (c < NTYPE) {
        int o = 0;
        for (int k = 0; k < c; k++) o += g_cnti[k];
        soff[c] = o;
    }
    if (c == NTYPE) soff[NTYPE] = batch;
    const int pstart = blockIdx.x * CHUNK;
    const int pend = min(pstart + CHUNK, batch);
    for (int j = c; j < pend - pstart; j += 128) sperm[j] = g_perm[pstart + j];
    __syncthreads();

    const bool sc = (c < 64);
    const bool h2 = (c < 112);
    const int c2 = c + 128;

    int curt = 0;
    while (pstart >= soff[curt + 1]) curt++;

    int p = pstart;
    while (p < pend) {
        const int rend = min(pend, soff[curt + 1]);
        float s0 = 0.f, s1 = 0.f, s2 = 0.f;
#pragma unroll 4
        for (int q = p; q < rend; q++) {
            const int row = sperm[q - pstart];
            const float* xr = x + (long long)row * DIMX;
            const float v  = __ldg(xr + c);
            const float v2 = h2 ? __ldg(xr + c2) : 0.0f;
            if (sc) {
                s0 += v;
                s1 = fmaf(v, v, s1);
            } else {
                s0 = fmaf(v, v, s0);
            }
            s2 = fmaf(v2, v2, s2);
        }
        float* g = g_acc + curt * NSLOT;
        if (sc) {
            atomicAdd(g + c, s0);
            atomicAdd(g + 64 + c, s1);
        } else {
            const int slot0 = (c < 160) ? (128 + (c - 64) / 3) : (160 + (c - 160) / 5);
            atomicAdd(g + slot0, s0);
        }
        if (h2) {
            const int slot2 = (c2 < 160) ? (128 + (c2 - 64) / 3) : (160 + (c2 - 160) / 5);
            atomicAdd(g + slot2, s2);
        }
        p = rend;
        if (p < pend) {
            while (p >= soff[curt + 1]) curt++;
        }
    }
}

__global__ void k_stats(const float* __restrict__ w, const float* __restrict__ b) {
    const int t = blockIdx.x;
    const int c = threadIdx.x;
    const float cnt = fmaxf((float)g_cnti[t], 1.0f);
    const float* acc = g_acc + t * NSLOT;
    float A, C;
    if (c < 64) {
        const float fm  = acc[c] / cnt;
        const float var = acc[64 + c] / cnt - fm * fm;
        const float s   = rsqrtf(var + EPSV) * w[t * 112 + c];
        A = s;
        C = b[t * 64 + c] - fm * s;
    } else if (c < 160) {
        const int m = (c - 64) / 3;
        const float fn = acc[128 + m] / (3.0f * cnt);
        A = rsqrtf(fn + EPSV) * w[t * 112 + 64 + m];
        C = 0.0f;
    } else {
        const int m = (c - 160) / 5;
        const float fn = acc[160 + m] / (5.0f * cnt);
        A = rsqrtf(fn + EPSV) * w[t * 112 + 96 + m];
        C = 0.0f;
    }
    g_A[t * DIMX + c] = A;
    g_C[t * DIMX + c] = C;
}

// out = x * A[type][col] + C[type][col].
// Tile = 4 rows = 240 float4 handled by 240 threads; U=4 tiles per iteration
// with ALL loads batched first (MLP_p1 = 8) to cover DRAM latency.
#define UAPP 4
__global__ void __launch_bounds__(240)
k_apply2(const float4* __restrict__ x4, const int* __restrict__ tp,
         float4* __restrict__ o4, int batch) {
    __shared__ __align__(16) float sA[NTYPE * DIMX];
    __shared__ __align__(16) float sC[NTYPE * DIMX];
    for (int i = threadIdx.x; i < NTYPE * DIMX; i += blockDim.x) {
        sA[i] = g_A[i];
        sC[i] = g_C[i];
    }
    __syncthreads();

    const int tid = threadIdx.x;
    const int r = tid / 60;        // row-within-tile, loop-invariant
    const int q = tid - r * 60;    // float4-within-row
    const int ntiles = (batch + 3) >> 2;
    const int ngrp = (ntiles + UAPP - 1) / UAPP;

    for (int g = blockIdx.x; g < ngrp; g += gridDim.x) {
        const int tile0 = g * UAPP;
        float4 xv[UAPP];
        int t[UAPP];
        bool ok[UAPP];
#pragma unroll
        for (int u = 0; u < UAPP; u++) {
            const int tile = tile0 + u;
            const int row = tile * 4 + r;
            ok[u] = (row < batch);
            if (ok[u]) {
                xv[u] = x4[(long long)tile * 240 + tid];
                t[u] = __ldg(tp + row);
            }
        }
#pragma unroll
        for (int u = 0; u < UAPP; u++) {
            if (ok[u]) {
                const int tile = tile0 + u;
                const float4 a  = *((const float4*)(sA + t[u] * DIMX) + q);
                const float4 cc = *((const float4*)(sC + t[u] * DIMX) + q);
                float4 res;
                res.x = fmaf(xv[u].x, a.x, cc.x);
                res.y = fmaf(xv[u].y, a.y, cc.y);
                res.z = fmaf(xv[u].z, a.z, cc.z);
                res.w = fmaf(xv[u].w, a.w, cc.w);
                o4[(long long)tile * 240 + tid] = res;
            }
        }
    }
}

extern "C" void kernel_launch(void* const* d_in, const int* in_sizes, int n_in,
                              void* d_out, int out_size) {
    const float* x  = (const float*)d_in[0];
    const int*   tp = (const int*)d_in[1];
    const float* w  = (const float*)d_in[2];
    const float* b  = (const float*)d_in[3];
    float* out = (float*)d_out;
    const int batch = in_sizes[1];

    const int nsb = (batch + CHUNK - 1) / CHUNK;

    k_zero<<<7, 256>>>();
    k_hist<<<296, 256>>>(tp, batch);
    k_scatter<<<(batch + 255) / 256, 256>>>(tp, batch);
    k_reduce2<<<nsb, 128>>>(x, batch);          // launch index 3 -> gets profiled
    k_stats<<<NTYPE, DIMX>>>(w, b);
    k_apply2<<<1184, 240>>>((const float4*)x, tp, (float4*)out, batch);
}

// round 11
// speedup vs baseline: 1.6449x; 1.5634x over previous
#include <cuda_runtime.h>

#define DIMX   240
#define NTYPE  10
#define EPSV   1e-5f
#define MAXB   200704
#define TPBT   64    // tiles per reduce block (4 rows each) = 256 rows
#define RU     4     // tile unroll

__device__ float g_sum[NTYPE * 64];    // scalar-channel sums
__device__ float g_sq[NTYPE * DIMX];   // per-column sum of squares
__device__ int   g_cnti[NTYPE];
__device__ int   g_cursor[NTYPE];
__device__ int   g_perm[MAXB];
__device__ float g_A[NTYPE * DIMX];
__device__ float g_C[NTYPE * DIMX];

__global__ void k_zero() {
    int i = blockIdx.x * blockDim.x + threadIdx.x;
    if (i < NTYPE * DIMX) g_sq[i] = 0.0f;
    if (i < NTYPE * 64) g_sum[i] = 0.0f;
    if (i < NTYPE) { g_cnti[i] = 0; g_cursor[i] = 0; }
}

__global__ void k_hist(const int* __restrict__ tp, int batch) {
    __shared__ int h[NTYPE];
    if (threadIdx.x < NTYPE) h[threadIdx.x] = 0;
    __syncthreads();
    for (int i = blockIdx.x * blockDim.x + threadIdx.x; i < batch;
         i += gridDim.x * blockDim.x) {
        atomicAdd(&h[tp[i]], 1);
    }
    __syncthreads();
    if (threadIdx.x < NTYPE) atomicAdd(&g_cnti[threadIdx.x], h[threadIdx.x]);
}

// Counting-sort scatter with inline 10-element scan of g_cnti.
__global__ void k_scatter(const int* __restrict__ tp, int batch) {
    __shared__ int h[NTYPE], base[NTYPE], soff[NTYPE];
    if (threadIdx.x < NTYPE) {
        h[threadIdx.x] = 0;
        int o = 0;
        for (int k = 0; k < threadIdx.x; k++) o += g_cnti[k];
        soff[threadIdx.x] = o;
    }
    __syncthreads();
    const int i = blockIdx.x * blockDim.x + threadIdx.x;
    int t = 0, loc = 0;
    if (i < batch) {
        t = tp[i];
        loc = atomicAdd(&h[t], 1);
    }
    __syncthreads();
    if (threadIdx.x < NTYPE && h[threadIdx.x] > 0)
        base[threadIdx.x] = soff[threadIdx.x] + atomicAdd(&g_cursor[threadIdx.x], h[threadIdx.x]);
    __syncthreads();
    if (i < batch) g_perm[base[t] + loc] = i;
}

__device__ __forceinline__ void flush_acc(int t, int q, bool sc,
                                          float* ssq, float* ssm) {
    float* gq = g_sq + t * DIMX + q * 4;
    atomicAdd(gq + 0, ssq[0]);
    atomicAdd(gq + 1, ssq[1]);
    atomicAdd(gq + 2, ssq[2]);
    atomicAdd(gq + 3, ssq[3]);
    ssq[0] = ssq[1] = ssq[2] = ssq[3] = 0.f;
    if (sc) {
        float* gs = g_sum + t * 64 + q * 4;
        atomicAdd(gs + 0, ssm[0]);
        atomicAdd(gs + 1, ssm[1]);
        atomicAdd(gs + 2, ssm[2]);
        atomicAdd(gs + 3, ssm[3]);
        ssm[0] = ssm[1] = ssm[2] = ssm[3] = 0.f;
    }
}

// float4 reduce over bucket-sorted rows. Tile = 4 rows; thread (r,q) owns
// float4 q of row r within each tile. RU tiles unrolled: all loads batched
// first (MLP_p1 = 4 x LDG.128 per thread) to cover DRAM latency.
__global__ void __launch_bounds__(256)
k_reduce3(const float4* __restrict__ x4, int batch) {
    __shared__ int soff[NTYPE + 1];
    __shared__ int sperm[TPBT * 4];
    const int tid = threadIdx.x;
    if (tid < NTYPE) {
        int o = 0;
        for (int k = 0; k < tid; k++) o += g_cnti[k];
        soff[tid] = o;
    }
    if (tid == NTYPE) soff[NTYPE] = batch;
    const int row0 = blockIdx.x * (TPBT * 4);
    const int nrows = min(TPBT * 4, batch - row0);
    for (int j = tid; j < nrows; j += 256) sperm[j] = g_perm[row0 + j];
    __syncthreads();
    if (tid >= 240) return;

    const int r = tid / 60;
    const int q = tid - r * 60;
    const bool sc = (q < 16);   // scalar quad (cols 0..63)

    const int p0 = row0 + r;
    if (p0 >= batch) return;
    int curt = 0;
    while (p0 >= soff[curt + 1]) curt++;

    float ssq[4] = {0.f, 0.f, 0.f, 0.f};
    float ssm[4] = {0.f, 0.f, 0.f, 0.f};

    for (int tb = 0; tb < TPBT; tb += RU) {
        float4 v[RU];
        bool ok[RU];
#pragma unroll
        for (int u = 0; u < RU; u++) {
            const int j = (tb + u) * 4 + r;
            ok[u] = (j < nrows);
            if (ok[u]) {
                const int row = sperm[j];
                v[u] = x4[(long long)row * 60 + q];
            }
        }
#pragma unroll
        for (int u = 0; u < RU; u++) {
            if (!ok[u]) continue;
            const int p = row0 + (tb + u) * 4 + r;
            if (p >= soff[curt + 1]) {
                flush_acc(curt, q, sc, ssq, ssm);
                while (p >= soff[curt + 1]) curt++;
            }
            ssq[0] = fmaf(v[u].x, v[u].x, ssq[0]);
            ssq[1] = fmaf(v[u].y, v[u].y, ssq[1]);
            ssq[2] = fmaf(v[u].z, v[u].z, ssq[2]);
            ssq[3] = fmaf(v[u].w, v[u].w, ssq[3]);
            if (sc) {
                ssm[0] += v[u].x;
                ssm[1] += v[u].y;
                ssm[2] += v[u].z;
                ssm[3] += v[u].w;
            }
        }
    }
    flush_acc(curt, q, sc, ssq, ssm);
}

__global__ void k_stats(const float* __restrict__ w, const float* __restrict__ b) {
    const int t = blockIdx.x;
    const int c = threadIdx.x;
    const float cnt = fmaxf((float)g_cnti[t], 1.0f);
    const float* sq = g_sq + t * DIMX;
    float A, C;
    if (c < 64) {
        const float fm  = g_sum[t * 64 + c] / cnt;
        const float var = sq[c] / cnt - fm * fm;
        const float s   = rsqrtf(var + EPSV) * w[t * 112 + c];
        A = s;
        C = b[t * 64 + c] - fm * s;
    } else if (c < 160) {
        const int m = (c - 64) / 3;
        const int base = 64 + 3 * m;
        const float fn = (sq[base] + sq[base + 1] + sq[base + 2]) / (3.0f * cnt);
        A = rsqrtf(fn + EPSV) * w[t * 112 + 64 + m];
        C = 0.0f;
    } else {
        const int m = (c - 160) / 5;
        const int base = 160 + 5 * m;
        const float fn = (sq[base] + sq[base + 1] + sq[base + 2] + sq[base + 3] + sq[base + 4])
                         / (5.0f * cnt);
        A = rsqrtf(fn + EPSV) * w[t * 112 + 96 + m];
        C = 0.0f;
    }
    g_A[t * DIMX + c] = A;
    g_C[t * DIMX + c] = C;
}

// out = x * A[type][col] + C[type][col]; 4-row tiles, U=4 unroll, loads batched.
#define UAPP 4
__global__ void __launch_bounds__(240)
k_apply2(const float4* __restrict__ x4, const int* __restrict__ tp,
         float4* __restrict__ o4, int batch) {
    __shared__ __align__(16) float sA[NTYPE * DIMX];
    __shared__ __align__(16) float sC[NTYPE * DIMX];
    for (int i = threadIdx.x; i < NTYPE * DIMX; i += blockDim.x) {
        sA[i] = g_A[i];
        sC[i] = g_C[i];
    }
    __syncthreads();

    const int tid = threadIdx.x;
    const int r = tid / 60;
    const int q = tid - r * 60;
    const int ntiles = (batch + 3) >> 2;
    const int ngrp = (ntiles + UAPP - 1) / UAPP;

    for (int g = blockIdx.x; g < ngrp; g += gridDim.x) {
        const int tile0 = g * UAPP;
        float4 xv[UAPP];
        int t[UAPP];
        bool ok[UAPP];
#pragma unroll
        for (int u = 0; u < UAPP; u++) {
            const int tile = tile0 + u;
            const int row = tile * 4 + r;
            ok[u] = (row < batch);
            if (ok[u]) {
                xv[u] = x4[(long long)tile * 240 + tid];
                t[u] = __ldg(tp + row);
            }
        }
#pragma unroll
        for (int u = 0; u < UAPP; u++) {
            if (ok[u]) {
                const int tile = tile0 + u;
                const float4 a  = *((const float4*)(sA + t[u] * DIMX) + q);
                const float4 cc = *((const float4*)(sC + t[u] * DIMX) + q);
                float4 res;
                res.x = fmaf(xv[u].x, a.x, cc.x);
                res.y = fmaf(xv[u].y, a.y, cc.y);
                res.z = fmaf(xv[u].z, a.z, cc.z);
                res.w = fmaf(xv[u].w, a.w, cc.w);
                o4[(long long)tile * 240 + tid] = res;
            }
        }
    }
}

extern "C" void kernel_launch(void* const* d_in, const int* in_sizes, int n_in,
                              void* d_out, int out_size) {
    const float* x  = (const float*)d_in[0];
    const int*   tp = (const int*)d_in[1];
    const float* w  = (const float*)d_in[2];
    const float* b  = (const float*)d_in[3];
    float* out = (float*)d_out;
    const int batch = in_sizes[1];

    k_zero<<<12, 256>>>();
    k_hist<<<296, 256>>>(tp, batch);
    k_scatter<<<(batch + 255) / 256, 256>>>(tp, batch);
    k_reduce3<<<(batch + TPBT * 4 - 1) / (TPBT * 4), 256>>>((const float4*)x, batch);
    k_stats<<<NTYPE, DIMX>>>(w, b);
    k_apply2<<<1184, 240>>>((const float4*)x, tp, (float4*)out, batch);
}

// round 13
// speedup vs baseline: 1.6740x; 1.0176x over previous
#include <cuda_runtime.h>

#define DIMX   240
#define NTYPE  10
#define EPSV   1e-5f
#define MAXB   200704
#define RPB    256   // rows per reduce block
#define RU     4     // slow-path unroll
#define RUF    8     // fast-path unroll

__device__ float g_sum[NTYPE * 64];    // scalar-channel sums
__device__ float g_sq[NTYPE * DIMX];   // per-column sum of squares
__device__ int   g_cnti[NTYPE];
__device__ int   g_cursor[NTYPE];
__device__ int   g_perm[MAXB];
__device__ float g_A[NTYPE * DIMX];
__device__ float g_C[NTYPE * DIMX];

__global__ void k_zero() {
    int i = blockIdx.x * blockDim.x + threadIdx.x;
    if (i < NTYPE * DIMX) g_sq[i] = 0.0f;
    if (i < NTYPE * 64) g_sum[i] = 0.0f;
    if (i < NTYPE) { g_cnti[i] = 0; g_cursor[i] = 0; }
}

__global__ void k_hist(const int* __restrict__ tp, int batch) {
    __shared__ int h[NTYPE];
    if (threadIdx.x < NTYPE) h[threadIdx.x] = 0;
    __syncthreads();
    for (int i = blockIdx.x * blockDim.x + threadIdx.x; i < batch;
         i += gridDim.x * blockDim.x) {
        atomicAdd(&h[tp[i]], 1);
    }
    __syncthreads();
    if (threadIdx.x < NTYPE) atomicAdd(&g_cnti[threadIdx.x], h[threadIdx.x]);
}

// Counting-sort scatter with inline 10-element scan of g_cnti.
__global__ void k_scatter(const int* __restrict__ tp, int batch) {
    __shared__ int h[NTYPE], base[NTYPE], soff[NTYPE];
    if (threadIdx.x < NTYPE) {
        h[threadIdx.x] = 0;
        int o = 0;
        for (int k = 0; k < threadIdx.x; k++) o += g_cnti[k];
        soff[threadIdx.x] = o;
    }
    __syncthreads();
    const int i = blockIdx.x * blockDim.x + threadIdx.x;
    int t = 0, loc = 0;
    if (i < batch) {
        t = tp[i];
        loc = atomicAdd(&h[t], 1);
    }
    __syncthreads();
    if (threadIdx.x < NTYPE && h[threadIdx.x] > 0)
        base[threadIdx.x] = soff[threadIdx.x] + atomicAdd(&g_cursor[threadIdx.x], h[threadIdx.x]);
    __syncthreads();
    if (i < batch) g_perm[base[t] + loc] = i;
}

__device__ __forceinline__ void flush_acc(int t, int q, bool sc,
                                          float* ssq, float* ssm) {
    float* gq = g_sq + t * DIMX + q * 4;
    atomicAdd(gq + 0, ssq[0]);
    atomicAdd(gq + 1, ssq[1]);
    atomicAdd(gq + 2, ssq[2]);
    atomicAdd(gq + 3, ssq[3]);
    ssq[0] = ssq[1] = ssq[2] = ssq[3] = 0.f;
    if (sc) {
        float* gs = g_sum + t * 64 + q * 4;
        atomicAdd(gs + 0, ssm[0]);
        atomicAdd(gs + 1, ssm[1]);
        atomicAdd(gs + 2, ssm[2]);
        atomicAdd(gs + 3, ssm[3]);
        ssm[0] = ssm[1] = ssm[2] = ssm[3] = 0.f;
    }
}

// float4 reduce over bucket-sorted rows. Tile = 4 rows; thread (r,q) owns
// float4 q of row r within each tile. Fast path: block entirely inside one
// type bucket and full -> RUF=8 batched LDG.128, no per-element compares.
__global__ void __launch_bounds__(256)
k_reduce4(const float4* __restrict__ x4, int batch) {
    __shared__ int soff[NTYPE + 1];
    __shared__ int sperm[RPB];
    const int tid = threadIdx.x;
    if (tid < NTYPE) {
        int o = 0;
        for (int k = 0; k < tid; k++) o += g_cnti[k];
        soff[tid] = o;
    }
    if (tid == NTYPE) soff[NTYPE] = batch;
    const int row0 = blockIdx.x * RPB;
    const int nrows = min(RPB, batch - row0);
    for (int j = tid; j < nrows; j += 256) sperm[j] = g_perm[row0 + j];
    __syncthreads();
    if (tid >= 240) return;

    const int r = tid / 60;
    const int q = tid - r * 60;
    const bool sc = (q < 16);   // scalar quad (cols 0..63)

    int tA = 0;
    while (row0 >= soff[tA + 1]) tA++;
    int tB = tA;
    while (row0 + nrows - 1 >= soff[tB + 1]) tB++;

    float ssq[4] = {0.f, 0.f, 0.f, 0.f};
    float ssm[4] = {0.f, 0.f, 0.f, 0.f};

    if (tA == tB && nrows == RPB) {
        // ---- fast path: single type, full block ----
#pragma unroll 1
        for (int j0 = 0; j0 < RPB / 4; j0 += RUF) {
            float4 v[RUF];
#pragma unroll
            for (int u = 0; u < RUF; u++) {
                const unsigned row = (unsigned)sperm[(j0 + u) * 4 + r];
                v[u] = x4[row * 60u + (unsigned)q];
            }
#pragma unroll
            for (int u = 0; u < RUF; u++) {
                ssq[0] = fmaf(v[u].x, v[u].x, ssq[0]);
                ssq[1] = fmaf(v[u].y, v[u].y, ssq[1]);
                ssq[2] = fmaf(v[u].z, v[u].z, ssq[2]);
                ssq[3] = fmaf(v[u].w, v[u].w, ssq[3]);
                if (sc) {
                    ssm[0] += v[u].x;
                    ssm[1] += v[u].y;
                    ssm[2] += v[u].z;
                    ssm[3] += v[u].w;
                }
            }
        }
        flush_acc(tA, q, sc, ssq, ssm);
        return;
    }

    // ---- slow path: boundary or partial block ----
    const int p0 = row0 + r;
    if (p0 >= batch) return;
    int curt = tA;
    while (p0 >= soff[curt + 1]) curt++;

    for (int tb = 0; tb < RPB / 4; tb += RU) {
        float4 v[RU];
        bool ok[RU];
#pragma unroll
        for (int u = 0; u < RU; u++) {
            const int j = (tb + u) * 4 + r;
            ok[u] = (j < nrows);
            if (ok[u]) {
                const unsigned row = (unsigned)sperm[j];
                v[u] = x4[row * 60u + (unsigned)q];
            }
        }
#pragma unroll
        for (int u = 0; u < RU; u++) {
            if (!ok[u]) continue;
            const int p = row0 + (tb + u) * 4 + r;
            if (p >= soff[curt + 1]) {
                flush_acc(curt, q, sc, ssq, ssm);
                while (p >= soff[curt + 1]) curt++;
            }
            ssq[0] = fmaf(v[u].x, v[u].x, ssq[0]);
            ssq[1] = fmaf(v[u].y, v[u].y, ssq[1]);
            ssq[2] = fmaf(v[u].z, v[u].z, ssq[2]);
            ssq[3] = fmaf(v[u].w, v[u].w, ssq[3]);
            if (sc) {
                ssm[0] += v[u].x;
                ssm[1] += v[u].y;
                ssm[2] += v[u].z;
                ssm[3] += v[u].w;
            }
        }
    }
    flush_acc(curt, q, sc, ssq, ssm);
}

__global__ void k_stats(const float* __restrict__ w, const float* __restrict__ b) {
    const int t = blockIdx.x;
    const int c = threadIdx.x;
    const float cnt = fmaxf((float)g_cnti[t], 1.0f);
    const float* sq = g_sq + t * DIMX;
    float A, C;
    if (c < 64) {
        const float fm  = g_sum[t * 64 + c] / cnt;
        const float var = sq[c] / cnt - fm * fm;
        const float s   = rsqrtf(var + EPSV) * w[t * 112 + c];
        A = s;
        C = b[t * 64 + c] - fm * s;
    } else if (c < 160) {
        const int m = (c - 64) / 3;
        const int base = 64 + 3 * m;
        const float fn = (sq[base] + sq[base + 1] + sq[base + 2]) / (3.0f * cnt);
        A = rsqrtf(fn + EPSV) * w[t * 112 + 64 + m];
        C = 0.0f;
    } else {
        const int m = (c - 160) / 5;
        const int base = 160 + 5 * m;
        const float fn = (sq[base] + sq[base + 1] + sq[base + 2] + sq[base + 3] + sq[base + 4])
                         / (5.0f * cnt);
        A = rsqrtf(fn + EPSV) * w[t * 112 + 96 + m];
        C = 0.0f;
    }
    g_A[t * DIMX + c] = A;
    g_C[t * DIMX + c] = C;
}

// out = x * A[type][col] + C[type][col]; 4-row tiles, U=4 unroll, loads batched.
#define UAPP 4
__global__ void __launch_bounds__(240)
k_apply2(const float4* __restrict__ x4, const int* __restrict__ tp,
         float4* __restrict__ o4, int batch) {
    __shared__ __align__(16) float sA[NTYPE * DIMX];
    __shared__ __align__(16) float sC[NTYPE * DIMX];
    for (int i = threadIdx.x; i < NTYPE * DIMX; i += blockDim.x) {
        sA[i] = g_A[i];
        sC[i] = g_C[i];
    }
    __syncthreads();

    const int tid = threadIdx.x;
    const int r = tid / 60;
    const int q = tid - r * 60;
    const int ntiles = (batch + 3) >> 2;
    const int ngrp = (ntiles + UAPP - 1) / UAPP;

    for (int g = blockIdx.x; g < ngrp; g += gridDim.x) {
        const int tile0 = g * UAPP;
        float4 xv[UAPP];
        int t[UAPP];
        bool ok[UAPP];
#pragma unroll
        for (int u = 0; u < UAPP; u++) {
            const int tile = tile0 + u;
            const int row = tile * 4 + r;
            ok[u] = (row < batch);
            if (ok[u]) {
                xv[u] = x4[(unsigned)tile * 240u + (unsigned)tid];
                t[u] = __ldg(tp + row);
            }
        }
#pragma unroll
        for (int u = 0; u < UAPP; u++) {
            if (ok[u]) {
                const int tile = tile0 + u;
                const float4 a  = *((const float4*)(sA + t[u] * DIMX) + q);
                const float4 cc = *((const float4*)(sC + t[u] * DIMX) + q);
                float4 res;
                res.x = fmaf(xv[u].x, a.x, cc.x);
                res.y = fmaf(xv[u].y, a.y, cc.y);
                res.z = fmaf(xv[u].z, a.z, cc.z);
                res.w = fmaf(xv[u].w, a.w, cc.w);
                o4[(unsigned)tile * 240u + (unsigned)tid] = res;
            }
        }
    }
}

extern "C" void kernel_launch(void* const* d_in, const int* in_sizes, int n_in,
                              void* d_out, int out_size) {
    const float* x  = (const float*)d_in[0];
    const int*   tp = (const int*)d_in[1];
    const float* w  = (const float*)d_in[2];
    const float* b  = (const float*)d_in[3];
    float* out = (float*)d_out;
    const int batch = in_sizes[1];

    k_zero<<<12, 256>>>();
    k_hist<<<296, 256>>>(tp, batch);
    k_scatter<<<(batch + 255) / 256, 256>>>(tp, batch);
    k_reduce4<<<(batch + RPB - 1) / RPB, 256>>>((const float4*)x, batch);
    k_stats<<<NTYPE, DIMX>>>(w, b);
    k_apply2<<<1184, 240>>>((const float4*)x, tp, (float4*)out, batch);
}